// round 5
// baseline (speedup 1.0000x reference)
#include <cuda_runtime.h>
#include <cuda_bf16.h>
#include <cuda_fp16.h>
#include <cstdint>

// Problem constants (shapes are fixed by the dataset)
#define NN 50000
#define EE 800000
#define HC 256      // HEADS*OUT_C
#define HEADS 4

// Scratch (device globals -- no allocation allowed in kernel_launch)
__device__ __half g_hf[(size_t)NN * HC];    // h in fp16, 25.6 MB
__device__ float g_asrc[NN * HEADS];
__device__ float g_adst[NN * HEADS];
__device__ float g_ealpha[(size_t)EE * HEADS];  // per-edge logits, 12.8 MB
__device__ int   g_cnt[NN];
__device__ int   g_off[NN + 1];
__device__ int   g_cur[NN];
__device__ int   g_esrc[EE];
__device__ int   g_bsum[64];

// ---------------------------------------------------------------------------
__global__ void zero_kernel(int n) {
    int i = blockIdx.x * blockDim.x + threadIdx.x;
    if (i < n) g_cnt[i] = 0;
    if (i < n * HEADS) { g_asrc[i] = 0.f; g_adst[i] = 0.f; }
}

// ---------------------------------------------------------------------------
// Tensor-core GEMM: h[M,256] = X[M,256] * W[256,256] in fp32-equivalent
// precision via 3-term bf16 split. Epilogue: store h as fp16 AND fuse the
// attention dot products (a_src/a_dst) via quad-reduced atomics.
// Tile: BM=128, BN=128, BK=32. 8 warps (2x4), warp tile 64x32, mma m16n8k16.

#define BM 128
#define BN 128
#define BK 32
#define LDA 40   // smem row stride in bf16 elems (80B) -> conflict-free frags

__device__ __forceinline__ void split2(float x, float y,
                                       uint32_t& hi, uint32_t& lo) {
    __nv_bfloat16 hx = __float2bfloat16_rn(x);
    __nv_bfloat16 hy = __float2bfloat16_rn(y);
    __nv_bfloat16 lx = __float2bfloat16_rn(x - __bfloat162float(hx));
    __nv_bfloat16 ly = __float2bfloat16_rn(y - __bfloat162float(hy));
    hi = ((uint32_t)__bfloat16_as_ushort(hy) << 16) | __bfloat16_as_ushort(hx);
    lo = ((uint32_t)__bfloat16_as_ushort(ly) << 16) | __bfloat16_as_ushort(lx);
}

__device__ __forceinline__ void mma_bf16(float* c,
    uint32_t a0, uint32_t a1, uint32_t a2, uint32_t a3,
    uint32_t b0, uint32_t b1)
{
    asm volatile(
        "mma.sync.aligned.m16n8k16.row.col.f32.bf16.bf16.f32 "
        "{%0,%1,%2,%3}, {%4,%5,%6,%7}, {%8,%9}, {%0,%1,%2,%3};"
        : "+f"(c[0]), "+f"(c[1]), "+f"(c[2]), "+f"(c[3])
        : "r"(a0), "r"(a1), "r"(a2), "r"(a3), "r"(b0), "r"(b1));
}

__global__ __launch_bounds__(256) void gemm_bf16x3_kernel(
    const float* __restrict__ X, const float* __restrict__ Wm,
    const float* __restrict__ att_src, const float* __restrict__ att_dst,
    int M)
{
    __shared__ __nv_bfloat16 Ah[BM * LDA];
    __shared__ __nv_bfloat16 Al[BM * LDA];
    __shared__ __nv_bfloat16 Bh[BN * LDA];
    __shared__ __nv_bfloat16 Bl[BN * LDA];

    const int tid  = threadIdx.x;
    const int warp = tid >> 5;
    const int lane = tid & 31;
    const int gid  = lane >> 2;    // group id (row within 8)
    const int tig  = lane & 3;     // thread in group
    const int bm = blockIdx.y * BM;
    const int bn = blockIdx.x * BN;
    const int wm = (warp >> 2) * 64;   // warp row base within tile
    const int wn = (warp & 3) * 32;    // warp col base within tile

    float acc[4][4][4];
#pragma unroll
    for (int mi = 0; mi < 4; mi++)
#pragma unroll
        for (int ni = 0; ni < 4; ni++)
#pragma unroll
            for (int r = 0; r < 4; r++) acc[mi][ni][r] = 0.f;

    for (int k0 = 0; k0 < 256; k0 += BK) {
        // --- load & split A tile: 128 rows x 32 k (fp32) ---
        {
            int row  = tid >> 1;               // 0..127
            int cbase = (tid & 1) * 16;        // half-row of 16 floats
            int grow = bm + row;
            const float4* src =
                (const float4*)(X + (size_t)grow * 256 + k0 + cbase);
#pragma unroll
            for (int i = 0; i < 4; i++) {
                float4 v = (grow < M) ? src[i] : make_float4(0.f,0.f,0.f,0.f);
                uint32_t h0, l0, h1, l1;
                split2(v.x, v.y, h0, l0);
                split2(v.z, v.w, h1, l1);
                int off = row * LDA + cbase + i * 4;
                *(uint2*)&Ah[off] = make_uint2(h0, h1);
                *(uint2*)&Al[off] = make_uint2(l0, l1);
            }
        }
        // --- load & split B tile transposed: Bs[n][k] = W[k0+k][bn+n] ---
        {
            int k  = tid >> 3;            // 0..31
            int nb = (tid & 7) * 16;      // 16 n values
            const float4* src =
                (const float4*)(Wm + (size_t)(k0 + k) * 256 + bn + nb);
#pragma unroll
            for (int i = 0; i < 4; i++) {
                float4 v = src[i];
                float f[4] = {v.x, v.y, v.z, v.w};
#pragma unroll
                for (int j = 0; j < 4; j++) {
                    int n = nb + i * 4 + j;
                    __nv_bfloat16 hv = __float2bfloat16_rn(f[j]);
                    __nv_bfloat16 lv =
                        __float2bfloat16_rn(f[j] - __bfloat162float(hv));
                    Bh[n * LDA + k] = hv;
                    Bl[n * LDA + k] = lv;
                }
            }
        }
        __syncthreads();

#pragma unroll
        for (int kk = 0; kk < 2; kk++) {       // two k16 steps per BK
            const int c0 = kk * 16 + tig * 2;
            uint32_t ah[4][4], al[4][4], bh[4][2], bl[4][2];
#pragma unroll
            for (int mi = 0; mi < 4; mi++) {
                int r0 = (wm + mi * 16 + gid) * LDA;
                int r8 = r0 + 8 * LDA;
                ah[mi][0] = *(const uint32_t*)&Ah[r0 + c0];
                ah[mi][1] = *(const uint32_t*)&Ah[r8 + c0];
                ah[mi][2] = *(const uint32_t*)&Ah[r0 + c0 + 8];
                ah[mi][3] = *(const uint32_t*)&Ah[r8 + c0 + 8];
                al[mi][0] = *(const uint32_t*)&Al[r0 + c0];
                al[mi][1] = *(const uint32_t*)&Al[r8 + c0];
                al[mi][2] = *(const uint32_t*)&Al[r0 + c0 + 8];
                al[mi][3] = *(const uint32_t*)&Al[r8 + c0 + 8];
            }
#pragma unroll
            for (int ni = 0; ni < 4; ni++) {
                int n0 = (wn + ni * 8 + gid) * LDA;
                bh[ni][0] = *(const uint32_t*)&Bh[n0 + c0];
                bh[ni][1] = *(const uint32_t*)&Bh[n0 + c0 + 8];
                bl[ni][0] = *(const uint32_t*)&Bl[n0 + c0];
                bl[ni][1] = *(const uint32_t*)&Bl[n0 + c0 + 8];
            }
#pragma unroll
            for (int mi = 0; mi < 4; mi++)
#pragma unroll
                for (int ni = 0; ni < 4; ni++) {
                    mma_bf16(acc[mi][ni], ah[mi][0], ah[mi][1], ah[mi][2],
                             ah[mi][3], bh[ni][0], bh[ni][1]);
                    mma_bf16(acc[mi][ni], ah[mi][0], ah[mi][1], ah[mi][2],
                             ah[mi][3], bl[ni][0], bl[ni][1]);
                    mma_bf16(acc[mi][ni], al[mi][0], al[mi][1], al[mi][2],
                             al[mi][3], bh[ni][0], bh[ni][1]);
                }
        }
        __syncthreads();
    }

    // --- epilogue: fp16 store of h + fused attention dot partials ---
    const int head = (bn + wn) >> 6;    // this thread's 8 cols share one head
#pragma unroll
    for (int mi = 0; mi < 4; mi++) {
        int r0 = bm + wm + mi * 16 + gid;
        int r1 = r0 + 8;
        float ps0 = 0.f, pd0 = 0.f, ps1 = 0.f, pd1 = 0.f;
#pragma unroll
        for (int ni = 0; ni < 4; ni++) {
            int col = bn + wn + ni * 8 + tig * 2;
            float as0 = att_src[col], as1 = att_src[col + 1];
            float ad0 = att_dst[col], ad1 = att_dst[col + 1];
            ps0 += acc[mi][ni][0] * as0 + acc[mi][ni][1] * as1;
            pd0 += acc[mi][ni][0] * ad0 + acc[mi][ni][1] * ad1;
            ps1 += acc[mi][ni][2] * as0 + acc[mi][ni][3] * as1;
            pd1 += acc[mi][ni][2] * ad0 + acc[mi][ni][3] * ad1;
            if (r0 < M)
                *(__half2*)(g_hf + (size_t)r0 * 256 + col) =
                    __floats2half2_rn(acc[mi][ni][0], acc[mi][ni][1]);
            if (r1 < M)
                *(__half2*)(g_hf + (size_t)r1 * 256 + col) =
                    __floats2half2_rn(acc[mi][ni][2], acc[mi][ni][3]);
        }
        // reduce across the 4 tig lanes (same output row) -> 1 atomic per row
        ps0 += __shfl_xor_sync(0xffffffffu, ps0, 1);
        ps0 += __shfl_xor_sync(0xffffffffu, ps0, 2);
        pd0 += __shfl_xor_sync(0xffffffffu, pd0, 1);
        pd0 += __shfl_xor_sync(0xffffffffu, pd0, 2);
        ps1 += __shfl_xor_sync(0xffffffffu, ps1, 1);
        ps1 += __shfl_xor_sync(0xffffffffu, ps1, 2);
        pd1 += __shfl_xor_sync(0xffffffffu, pd1, 1);
        pd1 += __shfl_xor_sync(0xffffffffu, pd1, 2);
        if (tig == 0) {
            if (r0 < M) {
                atomicAdd(&g_asrc[r0 * HEADS + head], ps0);
                atomicAdd(&g_adst[r0 * HEADS + head], pd0);
            }
            if (r1 < M) {
                atomicAdd(&g_asrc[r1 * HEADS + head], ps1);
                atomicAdd(&g_adst[r1 * HEADS + head], pd1);
            }
        }
    }
}

// ---------------------------------------------------------------------------
// edge_index arrives as int32 (JAX x64 disabled -> int64 randint is int32).
__global__ void hist_kernel(const int* __restrict__ ei, int E) {
    int i = blockIdx.x * blockDim.x + threadIdx.x;
    if (i < E) {
        int d = ei[E + i];
        atomicAdd(&g_cnt[d], 1);
    }
}

// ---------------------------------------------------------------------------
// Parallel scan: per-block scan -> block-sums scan -> carry add.
__global__ __launch_bounds__(1024) void scan1_kernel(int n) {
    __shared__ int sd[1024];
    int i = blockIdx.x * 1024 + threadIdx.x;
    int v = (i < n) ? g_cnt[i] : 0;
    sd[threadIdx.x] = v;
    __syncthreads();
#pragma unroll
    for (int o = 1; o < 1024; o <<= 1) {
        int t = (threadIdx.x >= (unsigned)o) ? sd[threadIdx.x - o] : 0;
        __syncthreads();
        sd[threadIdx.x] += t;
        __syncthreads();
    }
    if (i < n) g_off[i] = sd[threadIdx.x] - v;   // block-local exclusive
    if (threadIdx.x == 1023) g_bsum[blockIdx.x] = sd[1023];
}

__global__ void scan2_kernel(int nb, int n) {   // 1 block, 64 threads
    __shared__ int sd[64];
    int v = (threadIdx.x < (unsigned)nb) ? g_bsum[threadIdx.x] : 0;
    sd[threadIdx.x] = v;
    __syncthreads();
#pragma unroll
    for (int o = 1; o < 64; o <<= 1) {
        int t = (threadIdx.x >= (unsigned)o) ? sd[threadIdx.x - o] : 0;
        __syncthreads();
        sd[threadIdx.x] += t;
        __syncthreads();
    }
    if (threadIdx.x < (unsigned)nb) g_bsum[threadIdx.x] = sd[threadIdx.x] - v;
    if (threadIdx.x == (unsigned)(nb - 1)) g_off[n] = sd[threadIdx.x];
}

__global__ __launch_bounds__(1024) void scan3_kernel(int n) {
    int i = blockIdx.x * 1024 + threadIdx.x;
    if (i < n) {
        int o = g_off[i] + g_bsum[blockIdx.x];
        g_off[i] = o;
        g_cur[i] = o;
    }
}

// ---------------------------------------------------------------------------
// Scatter edges into CSR slots AND precompute per-edge logits
// alpha[e][h] = leakyrelu(a_src[s][h] + a_dst[d][h]).
__global__ void scatter_kernel(const int* __restrict__ ei, int E) {
    int i = blockIdx.x * blockDim.x + threadIdx.x;
    if (i < E) {
        int s = ei[i];
        int d = ei[E + i];
        int p = atomicAdd(&g_cur[d], 1);
        g_esrc[p] = s;
        float4 as = *(const float4*)(g_asrc + s * HEADS);
        float4 ad = *(const float4*)(g_adst + d * HEADS);
        float4 a;
        a.x = as.x + ad.x; a.x = (a.x >= 0.f) ? a.x : 0.2f * a.x;
        a.y = as.y + ad.y; a.y = (a.y >= 0.f) ? a.y : 0.2f * a.y;
        a.z = as.z + ad.z; a.z = (a.z >= 0.f) ? a.z : 0.2f * a.z;
        a.w = as.w + ad.w; a.w = (a.w >= 0.f) ? a.w : 0.2f * a.w;
        *(float4*)(g_ealpha + (size_t)p * HEADS) = a;
    }
}

// ---------------------------------------------------------------------------
// One warp per destination node: single-pass online segment softmax +
// weighted gather of fp16 features. Logits come precomputed (g_ealpha,
// coalesced stream) so the only gather is the feature vector, which is
// software-pipelined one edge ahead.
// lane l handles flat channels [l*8, l*8+8) -> head = l>>3 (8 lanes/head).
__global__ __launch_bounds__(256) void agg_kernel(
    const float* __restrict__ bias, float* __restrict__ out, int n)
{
    int d = (blockIdx.x * blockDim.x + threadIdx.x) >> 5;
    if (d >= n) return;
    int lane = threadIdx.x & 31;
    int hd = lane >> 3;

    int e0 = g_off[d], e1 = g_off[d + 1];

    // self-loop initializes the running state
    float aself = g_asrc[d * HEADS + hd] + g_adst[d * HEADS + hd];
    aself = (aself >= 0.f) ? aself : 0.2f * aself;
    float m = aself;
    float denom = 1.f;

    const size_t base = (size_t)d * 256 + lane * 8;
    uint4 raw = *(const uint4*)(g_hf + base);
    float2 f0 = __half22float2(((__half2*)&raw)[0]);
    float2 f1 = __half22float2(((__half2*)&raw)[1]);
    float2 f2 = __half22float2(((__half2*)&raw)[2]);
    float2 f3 = __half22float2(((__half2*)&raw)[3]);
    float acc[8] = { f0.x, f0.y, f1.x, f1.y, f2.x, f2.y, f3.x, f3.y };

    // 1-deep software pipeline on (alpha, features)
    float al0 = 0.f;
    uint4 r0 = make_uint4(0, 0, 0, 0);
    if (e0 < e1) {
        int s = g_esrc[e0];
        al0 = g_ealpha[(size_t)e0 * HEADS + hd];
        r0 = *(const uint4*)(g_hf + (size_t)s * 256 + lane * 8);
    }
    for (int e = e0; e < e1; e++) {
        float al1 = 0.f;
        uint4 r1 = make_uint4(0, 0, 0, 0);
        if (e + 1 < e1) {
            int s = g_esrc[e + 1];
            al1 = g_ealpha[(size_t)(e + 1) * HEADS + hd];
            r1 = *(const uint4*)(g_hf + (size_t)s * 256 + lane * 8);
        }
        float al = al0;
        float mn = fmaxf(m, al);
        float scale = __expf(m - mn);
        float ex = __expf(al - mn);
        m = mn;
        denom = denom * scale + ex;
        float2 w0 = __half22float2(((__half2*)&r0)[0]);
        float2 w1 = __half22float2(((__half2*)&r0)[1]);
        float2 w2 = __half22float2(((__half2*)&r0)[2]);
        float2 w3 = __half22float2(((__half2*)&r0)[3]);
        acc[0] = fmaf(acc[0], scale, ex * w0.x);
        acc[1] = fmaf(acc[1], scale, ex * w0.y);
        acc[2] = fmaf(acc[2], scale, ex * w1.x);
        acc[3] = fmaf(acc[3], scale, ex * w1.y);
        acc[4] = fmaf(acc[4], scale, ex * w2.x);
        acc[5] = fmaf(acc[5], scale, ex * w2.y);
        acc[6] = fmaf(acc[6], scale, ex * w3.x);
        acc[7] = fmaf(acc[7], scale, ex * w3.y);
        al0 = al1;
        r0 = r1;
    }

    float inv = 1.f / (denom + 1e-16f);
    float4 b0 = *(const float4*)(bias + lane * 8 + 0);
    float4 b1 = *(const float4*)(bias + lane * 8 + 4);
    float4 o0 = make_float4(acc[0]*inv + b0.x, acc[1]*inv + b0.y,
                            acc[2]*inv + b0.z, acc[3]*inv + b0.w);
    float4 o1 = make_float4(acc[4]*inv + b1.x, acc[5]*inv + b1.y,
                            acc[6]*inv + b1.z, acc[7]*inv + b1.w);
    *(float4*)(out + base + 0) = o0;
    *(float4*)(out + base + 4) = o1;
}

// ---------------------------------------------------------------------------
extern "C" void kernel_launch(void* const* d_in, const int* in_sizes, int n_in,
                              void* d_out, int out_size)
{
    const float* x       = (const float*)d_in[0];
    const int*   ei      = (const int*)d_in[1];     // int32 edge index [2, E]
    const float* W       = (const float*)d_in[2];
    const float* att_src = (const float*)d_in[3];
    const float* att_dst = (const float*)d_in[4];
    const float* bias    = (const float*)d_in[5];
    float*       out     = (float*)d_out;

    int n = in_sizes[0] / 256;      // 50000
    int E = in_sizes[1] / 2;        // 800000
    int nb = (n + 1023) / 1024;

    // Order chosen so the GEMM is the 4th launch (ncu captures index 3).
    zero_kernel<<<(n * HEADS + 255) / 256, 256>>>(n);
    hist_kernel<<<(E + 255) / 256, 256>>>(ei, E);
    scan1_kernel<<<nb, 1024>>>(n);

    dim3 ggrid(2, (n + BM - 1) / BM);
    gemm_bf16x3_kernel<<<ggrid, 256>>>(x, W, att_src, att_dst, n);

    scan2_kernel<<<1, 64>>>(nb, n);
    scan3_kernel<<<nb, 1024>>>(n);
    scatter_kernel<<<(E + 255) / 256, 256>>>(ei, E);

    agg_kernel<<<(n * 32 + 255) / 256, 256>>>(bias, out, n);
}

// round 6
// speedup vs baseline: 1.2848x; 1.2848x over previous
#include <cuda_runtime.h>
#include <cuda_bf16.h>
#include <cuda_fp16.h>
#include <cstdint>

// Problem constants (shapes are fixed by the dataset)
#define NN 50000
#define EE 800000
#define HC 256      // HEADS*OUT_C
#define HEADS 4

// Scratch (device globals -- no allocation allowed in kernel_launch)
__device__ __half g_hf[(size_t)NN * HC];    // h in fp16, 25.6 MB
__device__ float g_asrc[NN * HEADS];
__device__ float g_adst[NN * HEADS];
__device__ int   g_cnt[NN];
__device__ int   g_off[NN + 1];
__device__ int   g_cur[NN];
__device__ int   g_esrc[EE];
__device__ int   g_bsum[64];

// ---------------------------------------------------------------------------
__global__ void zero_kernel(int n) {
    int i = blockIdx.x * blockDim.x + threadIdx.x;
    if (i < n) g_cnt[i] = 0;
    if (i < n * HEADS) { g_asrc[i] = 0.f; g_adst[i] = 0.f; }
}

// ---------------------------------------------------------------------------
// Tensor-core GEMM: h[M,256] = X[M,256] * W[256,256] in fp32-equivalent
// precision via 3-term bf16 split. Fragments come from smem via ldmatrix
// (x4 for A, x4.trans for B). Epilogue: fp16 store of h + fused attention
// dots via quad-reduced atomics.
// Tile: BM=128, BN=128, BK=32. 8 warps (2x4), warp tile 64x32, mma m16n8k16.

#define BM 128
#define BN 128
#define BK 32
#define LDA 40    // A smem row stride (bf16), 80B -> conflict-free ldmatrix
#define LDB 136   // B smem row stride (bf16), 272B -> conflict-free .trans

__device__ __forceinline__ void split2(float x, float y,
                                       uint32_t& hi, uint32_t& lo) {
    __nv_bfloat16 hx = __float2bfloat16_rn(x);
    __nv_bfloat16 hy = __float2bfloat16_rn(y);
    __nv_bfloat16 lx = __float2bfloat16_rn(x - __bfloat162float(hx));
    __nv_bfloat16 ly = __float2bfloat16_rn(y - __bfloat162float(hy));
    hi = ((uint32_t)__bfloat16_as_ushort(hy) << 16) | __bfloat16_as_ushort(hx);
    lo = ((uint32_t)__bfloat16_as_ushort(ly) << 16) | __bfloat16_as_ushort(lx);
}

__device__ __forceinline__ void mma_bf16(float* c,
    uint32_t a0, uint32_t a1, uint32_t a2, uint32_t a3,
    uint32_t b0, uint32_t b1)
{
    asm volatile(
        "mma.sync.aligned.m16n8k16.row.col.f32.bf16.bf16.f32 "
        "{%0,%1,%2,%3}, {%4,%5,%6,%7}, {%8,%9}, {%0,%1,%2,%3};"
        : "+f"(c[0]), "+f"(c[1]), "+f"(c[2]), "+f"(c[3])
        : "r"(a0), "r"(a1), "r"(a2), "r"(a3), "r"(b0), "r"(b1));
}

__device__ __forceinline__ void ldsm_x4(uint32_t addr, uint32_t* r) {
    asm volatile(
        "ldmatrix.sync.aligned.m8n8.x4.shared.b16 {%0,%1,%2,%3}, [%4];"
        : "=r"(r[0]), "=r"(r[1]), "=r"(r[2]), "=r"(r[3]) : "r"(addr));
}

__device__ __forceinline__ void ldsm_x4_trans(uint32_t addr, uint32_t* r) {
    asm volatile(
        "ldmatrix.sync.aligned.m8n8.x4.trans.shared.b16 {%0,%1,%2,%3}, [%4];"
        : "=r"(r[0]), "=r"(r[1]), "=r"(r[2]), "=r"(r[3]) : "r"(addr));
}

__global__ __launch_bounds__(256) void gemm_bf16x3_kernel(
    const float* __restrict__ X, const float* __restrict__ Wm,
    const float* __restrict__ att_src, const float* __restrict__ att_dst,
    int M)
{
    __shared__ __nv_bfloat16 Ah[BM * LDA];   // [row][k]
    __shared__ __nv_bfloat16 Al[BM * LDA];
    __shared__ __nv_bfloat16 Bh[BK * LDB];   // [k][n]
    __shared__ __nv_bfloat16 Bl[BK * LDB];

    const int tid  = threadIdx.x;
    const int warp = tid >> 5;
    const int lane = tid & 31;
    const int gid  = lane >> 2;    // group id (row within 8)
    const int tig  = lane & 3;     // thread in group
    const int bm = blockIdx.y * BM;
    const int bn = blockIdx.x * BN;
    const int wm = (warp >> 2) * 64;   // warp row base within tile
    const int wn = (warp & 3) * 32;    // warp col base within tile

    const uint32_t ah_base = (uint32_t)__cvta_generic_to_shared(Ah);
    const uint32_t al_base = (uint32_t)__cvta_generic_to_shared(Al);
    const uint32_t bh_base = (uint32_t)__cvta_generic_to_shared(Bh);
    const uint32_t bl_base = (uint32_t)__cvta_generic_to_shared(Bl);

    float acc[4][4][4];
#pragma unroll
    for (int mi = 0; mi < 4; mi++)
#pragma unroll
        for (int ni = 0; ni < 4; ni++)
#pragma unroll
            for (int r = 0; r < 4; r++) acc[mi][ni][r] = 0.f;

    for (int k0 = 0; k0 < 256; k0 += BK) {
        // --- load & split A tile: 128 rows x 32 k (fp32), [row][k] ---
        {
            int row  = tid >> 1;               // 0..127
            int cbase = (tid & 1) * 16;        // half-row of 16 floats
            int grow = bm + row;
            const float4* src =
                (const float4*)(X + (size_t)grow * 256 + k0 + cbase);
#pragma unroll
            for (int i = 0; i < 4; i++) {
                float4 v = (grow < M) ? src[i] : make_float4(0.f,0.f,0.f,0.f);
                uint32_t h0, l0, h1, l1;
                split2(v.x, v.y, h0, l0);
                split2(v.z, v.w, h1, l1);
                int off = row * LDA + cbase + i * 4;
                *(uint2*)&Ah[off] = make_uint2(h0, h1);
                *(uint2*)&Al[off] = make_uint2(l0, l1);
            }
        }
        // --- load & split B tile: [k][n], coalesced both ways ---
        {
            int k  = tid >> 3;            // 0..31
            int nb = (tid & 7) * 16;      // 16 n values
            const float4* src =
                (const float4*)(Wm + (size_t)(k0 + k) * 256 + bn + nb);
#pragma unroll
            for (int i = 0; i < 4; i++) {
                float4 v = src[i];
                uint32_t h0, l0, h1, l1;
                split2(v.x, v.y, h0, l0);
                split2(v.z, v.w, h1, l1);
                int off = k * LDB + nb + i * 4;
                *(uint2*)&Bh[off] = make_uint2(h0, h1);
                *(uint2*)&Bl[off] = make_uint2(l0, l1);
            }
        }
        __syncthreads();

#pragma unroll
        for (int kk = 0; kk < 2; kk++) {       // two k16 steps per BK
            const int c0 = kk * 16;
            uint32_t ah[4][4], al[4][4], bh[4][2], bl[4][2];
            // A fragments: 16x16 per mi via ldmatrix.x4
            const uint32_t a_off =
                ((uint32_t)(wm + (lane & 15)) * LDA + c0 + ((lane >> 4) << 3)) * 2;
#pragma unroll
            for (int mi = 0; mi < 4; mi++) {
                ldsm_x4(ah_base + a_off + mi * 16 * LDA * 2, ah[mi]);
                ldsm_x4(al_base + a_off + mi * 16 * LDA * 2, al[mi]);
            }
            // B fragments: two n-blocks per ldmatrix.x4.trans
            const uint32_t b_off =
                ((uint32_t)(c0 + (lane & 15)) * LDB + wn + ((lane >> 4) << 3)) * 2;
#pragma unroll
            for (int nip = 0; nip < 2; nip++) {
                uint32_t t[4];
                ldsm_x4_trans(bh_base + b_off + nip * 16 * 2, t);
                bh[2*nip][0] = t[0]; bh[2*nip][1] = t[1];
                bh[2*nip+1][0] = t[2]; bh[2*nip+1][1] = t[3];
                ldsm_x4_trans(bl_base + b_off + nip * 16 * 2, t);
                bl[2*nip][0] = t[0]; bl[2*nip][1] = t[1];
                bl[2*nip+1][0] = t[2]; bl[2*nip+1][1] = t[3];
            }
#pragma unroll
            for (int mi = 0; mi < 4; mi++)
#pragma unroll
                for (int ni = 0; ni < 4; ni++) {
                    mma_bf16(acc[mi][ni], ah[mi][0], ah[mi][1], ah[mi][2],
                             ah[mi][3], bh[ni][0], bh[ni][1]);
                    mma_bf16(acc[mi][ni], ah[mi][0], ah[mi][1], ah[mi][2],
                             ah[mi][3], bl[ni][0], bl[ni][1]);
                    mma_bf16(acc[mi][ni], al[mi][0], al[mi][1], al[mi][2],
                             al[mi][3], bh[ni][0], bh[ni][1]);
                }
        }
        __syncthreads();
    }

    // --- epilogue: fp16 store of h + fused attention dot partials ---
    const int head = (bn + wn) >> 6;    // this thread's 8 cols share one head
#pragma unroll
    for (int mi = 0; mi < 4; mi++) {
        int r0 = bm + wm + mi * 16 + gid;
        int r1 = r0 + 8;
        float ps0 = 0.f, pd0 = 0.f, ps1 = 0.f, pd1 = 0.f;
#pragma unroll
        for (int ni = 0; ni < 4; ni++) {
            int col = bn + wn + ni * 8 + tig * 2;
            float as0 = att_src[col], as1 = att_src[col + 1];
            float ad0 = att_dst[col], ad1 = att_dst[col + 1];
            ps0 += acc[mi][ni][0] * as0 + acc[mi][ni][1] * as1;
            pd0 += acc[mi][ni][0] * ad0 + acc[mi][ni][1] * ad1;
            ps1 += acc[mi][ni][2] * as0 + acc[mi][ni][3] * as1;
            pd1 += acc[mi][ni][2] * ad0 + acc[mi][ni][3] * ad1;
            if (r0 < M)
                *(__half2*)(g_hf + (size_t)r0 * 256 + col) =
                    __floats2half2_rn(acc[mi][ni][0], acc[mi][ni][1]);
            if (r1 < M)
                *(__half2*)(g_hf + (size_t)r1 * 256 + col) =
                    __floats2half2_rn(acc[mi][ni][2], acc[mi][ni][3]);
        }
        // reduce across the 4 tig lanes (same output row) -> 1 atomic per row
        ps0 += __shfl_xor_sync(0xffffffffu, ps0, 1);
        ps0 += __shfl_xor_sync(0xffffffffu, ps0, 2);
        pd0 += __shfl_xor_sync(0xffffffffu, pd0, 1);
        pd0 += __shfl_xor_sync(0xffffffffu, pd0, 2);
        ps1 += __shfl_xor_sync(0xffffffffu, ps1, 1);
        ps1 += __shfl_xor_sync(0xffffffffu, ps1, 2);
        pd1 += __shfl_xor_sync(0xffffffffu, pd1, 1);
        pd1 += __shfl_xor_sync(0xffffffffu, pd1, 2);
        if (tig == 0) {
            if (r0 < M) {
                atomicAdd(&g_asrc[r0 * HEADS + head], ps0);
                atomicAdd(&g_adst[r0 * HEADS + head], pd0);
            }
            if (r1 < M) {
                atomicAdd(&g_asrc[r1 * HEADS + head], ps1);
                atomicAdd(&g_adst[r1 * HEADS + head], pd1);
            }
        }
    }
}

// ---------------------------------------------------------------------------
// edge_index arrives as int32 (JAX x64 disabled -> int64 randint is int32).
__global__ void hist_kernel(const int* __restrict__ ei, int E) {
    int i = blockIdx.x * blockDim.x + threadIdx.x;
    if (i < E) {
        int d = ei[E + i];
        atomicAdd(&g_cnt[d], 1);
    }
}

// ---------------------------------------------------------------------------
// Parallel scan: per-block scan -> block-sums scan -> carry add.
__global__ __launch_bounds__(1024) void scan1_kernel(int n) {
    __shared__ int sd[1024];
    int i = blockIdx.x * 1024 + threadIdx.x;
    int v = (i < n) ? g_cnt[i] : 0;
    sd[threadIdx.x] = v;
    __syncthreads();
#pragma unroll
    for (int o = 1; o < 1024; o <<= 1) {
        int t = (threadIdx.x >= (unsigned)o) ? sd[threadIdx.x - o] : 0;
        __syncthreads();
        sd[threadIdx.x] += t;
        __syncthreads();
    }
    if (i < n) g_off[i] = sd[threadIdx.x] - v;   // block-local exclusive
    if (threadIdx.x == 1023) g_bsum[blockIdx.x] = sd[1023];
}

__global__ void scan2_kernel(int nb, int n) {   // 1 block, 64 threads
    __shared__ int sd[64];
    int v = (threadIdx.x < (unsigned)nb) ? g_bsum[threadIdx.x] : 0;
    sd[threadIdx.x] = v;
    __syncthreads();
#pragma unroll
    for (int o = 1; o < 64; o <<= 1) {
        int t = (threadIdx.x >= (unsigned)o) ? sd[threadIdx.x - o] : 0;
        __syncthreads();
        sd[threadIdx.x] += t;
        __syncthreads();
    }
    if (threadIdx.x < (unsigned)nb) g_bsum[threadIdx.x] = sd[threadIdx.x] - v;
    if (threadIdx.x == (unsigned)(nb - 1)) g_off[n] = sd[threadIdx.x];
}

__global__ __launch_bounds__(1024) void scan3_kernel(int n) {
    int i = blockIdx.x * 1024 + threadIdx.x;
    if (i < n) {
        int o = g_off[i] + g_bsum[blockIdx.x];
        g_off[i] = o;
        g_cur[i] = o;
    }
}

__global__ void scatter_kernel(const int* __restrict__ ei, int E) {
    int i = blockIdx.x * blockDim.x + threadIdx.x;
    if (i < E) {
        int s = ei[i];
        int d = ei[E + i];
        int p = atomicAdd(&g_cur[d], 1);
        g_esrc[p] = s;
    }
}

// ---------------------------------------------------------------------------
// One warp per destination node: single-pass online segment softmax +
// weighted gather of fp16 features (logits fp32-exact).
// lane l handles flat channels [l*8, l*8+8) -> head = l>>3 (8 lanes/head).
__global__ __launch_bounds__(256) void agg_kernel(
    const float* __restrict__ bias, float* __restrict__ out, int n)
{
    int d = (blockIdx.x * blockDim.x + threadIdx.x) >> 5;
    if (d >= n) return;
    int lane = threadIdx.x & 31;
    int hd = lane >> 3;

    float adst_h = g_adst[d * HEADS + hd];
    int e0 = g_off[d], e1 = g_off[d + 1];

    // self-loop initializes the running state
    float aself = g_asrc[d * HEADS + hd] + adst_h;
    aself = (aself >= 0.f) ? aself : 0.2f * aself;
    float m = aself;
    float denom = 1.f;

    const size_t base = (size_t)d * 256 + lane * 8;
    uint4 raw = *(const uint4*)(g_hf + base);
    float2 f0 = __half22float2(((__half2*)&raw)[0]);
    float2 f1 = __half22float2(((__half2*)&raw)[1]);
    float2 f2 = __half22float2(((__half2*)&raw)[2]);
    float2 f3 = __half22float2(((__half2*)&raw)[3]);
    float acc[8] = { f0.x, f0.y, f1.x, f1.y, f2.x, f2.y, f3.x, f3.y };

    // software-pipelined edge loop (prefetch next a_src)
    int s_next = 0;
    float a_next = 0.f;
    if (e0 < e1) {
        s_next = g_esrc[e0];
        a_next = g_asrc[s_next * HEADS + hd];
    }
    for (int e = e0; e < e1; e++) {
        int s = s_next;
        float a_s = a_next;
        uint4 r = *(const uint4*)(g_hf + (size_t)s * 256 + lane * 8);
        if (e + 1 < e1) {
            s_next = g_esrc[e + 1];
            a_next = g_asrc[s_next * HEADS + hd];
        }
        float al = a_s + adst_h;
        al = (al >= 0.f) ? al : 0.2f * al;
        float mn = fmaxf(m, al);
        float scale = __expf(m - mn);
        float ex = __expf(al - mn);
        m = mn;
        denom = denom * scale + ex;
        float2 w0 = __half22float2(((__half2*)&r)[0]);
        float2 w1 = __half22float2(((__half2*)&r)[1]);
        float2 w2 = __half22float2(((__half2*)&r)[2]);
        float2 w3 = __half22float2(((__half2*)&r)[3]);
        acc[0] = fmaf(acc[0], scale, ex * w0.x);
        acc[1] = fmaf(acc[1], scale, ex * w0.y);
        acc[2] = fmaf(acc[2], scale, ex * w1.x);
        acc[3] = fmaf(acc[3], scale, ex * w1.y);
        acc[4] = fmaf(acc[4], scale, ex * w2.x);
        acc[5] = fmaf(acc[5], scale, ex * w2.y);
        acc[6] = fmaf(acc[6], scale, ex * w3.x);
        acc[7] = fmaf(acc[7], scale, ex * w3.y);
    }

    float inv = 1.f / (denom + 1e-16f);
    float4 b0 = *(const float4*)(bias + lane * 8 + 0);
    float4 b1 = *(const float4*)(bias + lane * 8 + 4);
    float4 o0 = make_float4(acc[0]*inv + b0.x, acc[1]*inv + b0.y,
                            acc[2]*inv + b0.z, acc[3]*inv + b0.w);
    float4 o1 = make_float4(acc[4]*inv + b1.x, acc[5]*inv + b1.y,
                            acc[6]*inv + b1.z, acc[7]*inv + b1.w);
    *(float4*)(out + base + 0) = o0;
    *(float4*)(out + base + 4) = o1;
}

// ---------------------------------------------------------------------------
extern "C" void kernel_launch(void* const* d_in, const int* in_sizes, int n_in,
                              void* d_out, int out_size)
{
    const float* x       = (const float*)d_in[0];
    const int*   ei      = (const int*)d_in[1];     // int32 edge index [2, E]
    const float* W       = (const float*)d_in[2];
    const float* att_src = (const float*)d_in[3];
    const float* att_dst = (const float*)d_in[4];
    const float* bias    = (const float*)d_in[5];
    float*       out     = (float*)d_out;

    int n = in_sizes[0] / 256;      // 50000
    int E = in_sizes[1] / 2;        // 800000
    int nb = (n + 1023) / 1024;

    // Order chosen so the GEMM is the 4th launch (ncu captures index 3).
    zero_kernel<<<(n * HEADS + 255) / 256, 256>>>(n);
    hist_kernel<<<(E + 255) / 256, 256>>>(ei, E);
    scan1_kernel<<<nb, 1024>>>(n);

    dim3 ggrid(2, (n + BM - 1) / BM);
    gemm_bf16x3_kernel<<<ggrid, 256>>>(x, W, att_src, att_dst, n);

    scan2_kernel<<<1, 64>>>(nb, n);
    scan3_kernel<<<nb, 1024>>>(n);
    scatter_kernel<<<(E + 255) / 256, 256>>>(ei, E);

    agg_kernel<<<(n * 32 + 255) / 256, 256>>>(bias, out, n);
}